// round 2
// baseline (speedup 1.0000x reference)
#include <cuda_runtime.h>
#include <cuda_bf16.h>
#include <math.h>

// Problem constants (fixed shapes for this problem instance)
#define N_NODES  50000
#define N_EDGES  1600000
#define IN_CH    64
#define HID      16
#define NCLS     10
#define HID2P    12   // padded width for layer-2 edge features (multiple of 4)

// ---------------- device scratch (no allocations allowed) ----------------
__device__ float g_y1  [N_NODES * HID];    // x @ w_rel1          [N,16]
__device__ float g_r1  [N_NODES * HID];    // x @ w_root1         [N,16]
__device__ float g_agg1[N_NODES * HID];    // segment_sum(y1)     [N,16]
__device__ float g_y2  [N_NODES * HID2P];  // h @ w_rel2 (padded) [N,12]
__device__ float g_r2  [N_NODES * HID2P];  // h @ w_root2         [N,12]
__device__ float g_agg2[N_NODES * HID2P];  // segment_sum(y2)     [N,12]
__device__ int   g_idx [N_EDGES * 2];      // converted int32 indices [src | dst]
__device__ int   g_is64;                   // 1 if edge_index buffer is int64

// ---------------- kernels ----------------

// Detect edge index dtype: if buffer is int64 with values < 2^31, every odd
// 32-bit word is zero. If int32, odd words are random node ids (nonzero w.h.p.).
__global__ void k_detect(const int* __restrict__ ei32) {
    __shared__ int s_or;
    if (threadIdx.x == 0) s_or = 0;
    __syncthreads();
    int v = 0;
    // inspect odd 32-bit words in the first 2048 words (within bounds for both dtypes)
    for (int i = threadIdx.x; i < 1024; i += blockDim.x)
        v |= ei32[2 * i + 1];
    if (v) atomicOr(&s_or, 1);
    __syncthreads();
    if (threadIdx.x == 0) g_is64 = (s_or == 0) ? 1 : 0;
}

// Convert edge indices to a flat int32 array (handles both int32 and int64 input)
__global__ void k_prep(const void* __restrict__ ei) {
    const int is64 = g_is64;
    const int n = N_EDGES * 2;
    if (is64) {
        const long long* p = (const long long*)ei;
        for (int i = blockIdx.x * blockDim.x + threadIdx.x; i < n;
             i += gridDim.x * blockDim.x)
            g_idx[i] = (int)p[i];
    } else {
        const int* p = (const int*)ei;
        for (int i = blockIdx.x * blockDim.x + threadIdx.x; i < n;
             i += gridDim.x * blockDim.x)
            g_idx[i] = p[i];
    }
}

// Zero both aggregation buffers (float4 grid-stride)
__global__ void k_zero() {
    const int n1 = N_NODES * HID / 4;     // 200000 float4
    const int n2 = N_NODES * HID2P / 4;   // 150000 float4
    float4 z = make_float4(0.f, 0.f, 0.f, 0.f);
    for (int i = blockIdx.x * blockDim.x + threadIdx.x; i < n1 + n2;
         i += gridDim.x * blockDim.x) {
        if (i < n1) reinterpret_cast<float4*>(g_agg1)[i] = z;
        else        reinterpret_cast<float4*>(g_agg2)[i - n1] = z;
    }
}

// Layer-1 projections: y1 = x @ w_rel1, r1 = x @ w_root1  (64 -> 16, twice)
__global__ __launch_bounds__(128) void k_lin1(const float* __restrict__ x,
                                              const float* __restrict__ w_rel,
                                              const float* __restrict__ w_root) {
    __shared__ float sw[IN_CH * HID];   // 4 KB
    __shared__ float su[IN_CH * HID];   // 4 KB
    for (int i = threadIdx.x; i < IN_CH * HID; i += 128) {
        sw[i] = w_rel[i];
        su[i] = w_root[i];
    }
    __syncthreads();

    int node = blockIdx.x * 128 + threadIdx.x;
    if (node >= N_NODES) return;

    float accR[HID], accT[HID];
#pragma unroll
    for (int j = 0; j < HID; j++) { accR[j] = 0.f; accT[j] = 0.f; }

    const float4* xr = reinterpret_cast<const float4*>(x + (size_t)node * IN_CH);
#pragma unroll
    for (int k4 = 0; k4 < IN_CH / 4; k4++) {
        float4 xv = __ldg(xr + k4);
        float xs[4] = {xv.x, xv.y, xv.z, xv.w};
#pragma unroll
        for (int t = 0; t < 4; t++) {
            int k = k4 * 4 + t;
#pragma unroll
            for (int j = 0; j < HID; j++) {
                accR[j] = fmaf(xs[t], sw[k * HID + j], accR[j]);
                accT[j] = fmaf(xs[t], su[k * HID + j], accT[j]);
            }
        }
    }
    float4* y1 = reinterpret_cast<float4*>(g_y1 + (size_t)node * HID);
    float4* r1 = reinterpret_cast<float4*>(g_r1 + (size_t)node * HID);
#pragma unroll
    for (int q = 0; q < 4; q++) {
        y1[q] = make_float4(accR[q*4+0], accR[q*4+1], accR[q*4+2], accR[q*4+3]);
        r1[q] = make_float4(accT[q*4+0], accT[q*4+1], accT[q*4+2], accT[q*4+3]);
    }
}

// Layer-1 scatter: agg1[dst] += y1[src]  (16 floats = 4x red.v4 per edge)
__global__ __launch_bounds__(256) void k_scat1() {
    int e = blockIdx.x * 256 + threadIdx.x;
    if (e >= N_EDGES) return;
    int s = g_idx[e];
    int d = g_idx[N_EDGES + e];
    const float4* srcp = reinterpret_cast<const float4*>(g_y1 + (size_t)s * HID);
    float* dstp = g_agg1 + (size_t)d * HID;
#pragma unroll
    for (int q = 0; q < 4; q++) {
        float4 v = __ldg(srcp + q);
        asm volatile("red.global.add.v4.f32 [%0], {%1, %2, %3, %4};"
                     :: "l"(dstp + q * 4), "f"(v.x), "f"(v.y), "f"(v.z), "f"(v.w)
                     : "memory");
    }
}

// h = relu(agg1 + b1 + r1); y2 = h @ w_rel2 (padded to 12); r2 = h @ w_root2
__global__ __launch_bounds__(128) void k_lin2(const float* __restrict__ b1,
                                              const float* __restrict__ w_rel2,
                                              const float* __restrict__ w_root2) {
    __shared__ float sw[HID * NCLS];   // 160 floats
    __shared__ float su[HID * NCLS];
    __shared__ float sb[HID];
    for (int i = threadIdx.x; i < HID * NCLS; i += 128) {
        sw[i] = w_rel2[i];
        su[i] = w_root2[i];
    }
    if (threadIdx.x < HID) sb[threadIdx.x] = b1[threadIdx.x];
    __syncthreads();

    int node = blockIdx.x * 128 + threadIdx.x;
    if (node >= N_NODES) return;

    float h[HID];
#pragma unroll
    for (int j = 0; j < HID; j++) {
        float v = g_agg1[(size_t)node * HID + j] + sb[j] + g_r1[(size_t)node * HID + j];
        h[j] = v > 0.f ? v : 0.f;
    }
    float y[NCLS], r[NCLS];
#pragma unroll
    for (int c = 0; c < NCLS; c++) { y[c] = 0.f; r[c] = 0.f; }
#pragma unroll
    for (int j = 0; j < HID; j++) {
#pragma unroll
        for (int c = 0; c < NCLS; c++) {
            y[c] = fmaf(h[j], sw[j * NCLS + c], y[c]);
            r[c] = fmaf(h[j], su[j * NCLS + c], r[c]);
        }
    }
    float* y2 = g_y2 + (size_t)node * HID2P;
    float* r2 = g_r2 + (size_t)node * HID2P;
#pragma unroll
    for (int c = 0; c < NCLS; c++) { y2[c] = y[c]; r2[c] = r[c]; }
    y2[10] = 0.f; y2[11] = 0.f;
    r2[10] = 0.f; r2[11] = 0.f;
}

// Layer-2 scatter: agg2[dst] += y2[src]  (12 floats = 3x red.v4 per edge)
__global__ __launch_bounds__(256) void k_scat2() {
    int e = blockIdx.x * 256 + threadIdx.x;
    if (e >= N_EDGES) return;
    int s = g_idx[e];
    int d = g_idx[N_EDGES + e];
    const float4* srcp = reinterpret_cast<const float4*>(g_y2 + (size_t)s * HID2P);
    float* dstp = g_agg2 + (size_t)d * HID2P;
#pragma unroll
    for (int q = 0; q < 3; q++) {
        float4 v = __ldg(srcp + q);
        asm volatile("red.global.add.v4.f32 [%0], {%1, %2, %3, %4};"
                     :: "l"(dstp + q * 4), "f"(v.x), "f"(v.y), "f"(v.z), "f"(v.w)
                     : "memory");
    }
}

// out = log_softmax(agg2 + b2 + r2)
__global__ __launch_bounds__(128) void k_out(const float* __restrict__ b2,
                                             float* __restrict__ out) {
    __shared__ float sb[NCLS];
    if (threadIdx.x < NCLS) sb[threadIdx.x] = b2[threadIdx.x];
    __syncthreads();

    int node = blockIdx.x * 128 + threadIdx.x;
    if (node >= N_NODES) return;

    float o[NCLS];
#pragma unroll
    for (int c = 0; c < NCLS; c++)
        o[c] = g_agg2[(size_t)node * HID2P + c] + sb[c] + g_r2[(size_t)node * HID2P + c];

    float m = o[0];
#pragma unroll
    for (int c = 1; c < NCLS; c++) m = fmaxf(m, o[c]);
    float sum = 0.f;
#pragma unroll
    for (int c = 0; c < NCLS; c++) sum += __expf(o[c] - m);
    float ls = m + logf(sum);
#pragma unroll
    for (int c = 0; c < NCLS; c++)
        out[(size_t)node * NCLS + c] = o[c] - ls;
}

// ---------------- launch ----------------
extern "C" void kernel_launch(void* const* d_in, const int* in_sizes, int n_in,
                              void* d_out, int out_size) {
    const float* x       = (const float*)d_in[0];
    const void*  ei      = d_in[1];
    const float* w_rel1  = (const float*)d_in[2];
    const float* b_rel1  = (const float*)d_in[3];
    const float* w_root1 = (const float*)d_in[4];
    const float* w_rel2  = (const float*)d_in[5];
    const float* b_rel2  = (const float*)d_in[6];
    const float* w_root2 = (const float*)d_in[7];
    float* out = (float*)d_out;

    const int nodeBlocks = (N_NODES + 127) / 128;
    const int edgeBlocks = (N_EDGES + 255) / 256;

    k_detect<<<1, 256>>>((const int*)ei);
    k_prep<<<1184, 256>>>(ei);
    k_zero<<<1184, 256>>>();
    k_lin1<<<nodeBlocks, 128>>>(x, w_rel1, w_root1);
    k_scat1<<<edgeBlocks, 256>>>();
    k_lin2<<<nodeBlocks, 128>>>(b_rel1, w_rel2, w_root2);
    k_scat2<<<edgeBlocks, 256>>>();
    k_out<<<nodeBlocks, 128>>>(b_rel2, out);
}